// round 9
// baseline (speedup 1.0000x reference)
#include <cuda_runtime.h>
#include <cstdint>

#define S_LEN   4096
#define DMODEL  1024
#define HEADS   16
#define DKV     64

// ---------------- scratch ---------------------------------------------------
__device__ float    g_att[S_LEN * DMODEL];       // fp32 [s, h*64+d]
__device__ uint32_t g_wqh[512 * 1024], g_wql[512 * 1024];
__device__ uint32_t g_wkh[512 * 64],   g_wkl[512 * 64];
__device__ uint32_t g_wvh[512 * 64],   g_wvl[512 * 64];
__device__ uint32_t g_woh[512 * 1024], g_wol[512 * 1024];
__device__ uint32_t g_qph[S_LEN * 512], g_qpl[S_LEN * 512];   // [s][dk-pair of dmodel]
__device__ uint32_t g_kph[S_LEN * 32], g_kpl[S_LEN * 32];     // [key][dk-pair]
__device__ uint32_t g_vth[64 * (S_LEN / 2)], g_vtl[64 * (S_LEN / 2)]; // [dk][key-pair]

// ---------------- bf16 helpers ----------------------------------------------
__device__ __forceinline__ void split2(float x, float y, uint32_t& h, uint32_t& l) {
    uint32_t hp;
    asm("cvt.rn.bf16x2.f32 %0,%1,%2;" : "=r"(hp) : "f"(y), "f"(x));
    float hx = __uint_as_float(hp << 16);
    float hy = __uint_as_float(hp & 0xffff0000u);
    asm("cvt.rn.bf16x2.f32 %0,%1,%2;" : "=r"(l) : "f"(y - hy), "f"(x - hx));
    h = hp;
}
__device__ __forceinline__ void mma_bf16(float* d, const uint32_t* a,
                                         uint32_t b0, uint32_t b1) {
    asm volatile("mma.sync.aligned.m16n8k16.row.col.f32.bf16.bf16.f32 "
        "{%0,%1,%2,%3},{%4,%5,%6,%7},{%8,%9},{%0,%1,%2,%3};"
        : "+f"(d[0]), "+f"(d[1]), "+f"(d[2]), "+f"(d[3])
        : "r"(a[0]), "r"(a[1]), "r"(a[2]), "r"(a[3]), "r"(b0), "r"(b1));
}
__device__ __forceinline__ void ldsm4(uint32_t& r0, uint32_t& r1,
                                      uint32_t& r2, uint32_t& r3, uint32_t addr) {
    asm volatile("ldmatrix.sync.aligned.m8n8.x4.shared.b16 {%0,%1,%2,%3}, [%4];"
                 : "=r"(r0), "=r"(r1), "=r"(r2), "=r"(r3) : "r"(addr));
}
__device__ __forceinline__ uint32_t smem_u32(const void* p) {
    uint32_t a;
    asm("{ .reg .u64 t; cvta.to.shared.u64 t, %1; cvt.u32.u64 %0, t; }"
        : "=r"(a) : "l"(p));
    return a;
}
__device__ __forceinline__ void cp16(uint32_t saddr, const void* g) {
    asm volatile("cp.async.cg.shared.global [%0], [%1], 16;" :: "r"(saddr), "l"(g));
}
#define CP_COMMIT() asm volatile("cp.async.commit_group;" ::: "memory")
#define CP_WAIT0()  asm volatile("cp.async.wait_group 0;"  ::: "memory")

// ---------------- combined weight pre-split ---------------------------------
__global__ __launch_bounds__(256)
void splitAll(const float* __restrict__ Wq, const float* __restrict__ Wo,
              const float* __restrict__ Wk, const float* __restrict__ Wv,
              uint32_t* __restrict__ wqh, uint32_t* __restrict__ wql,
              uint32_t* __restrict__ woh, uint32_t* __restrict__ wol,
              uint32_t* __restrict__ wkh, uint32_t* __restrict__ wkl,
              uint32_t* __restrict__ wvh, uint32_t* __restrict__ wvl)
{
    constexpr int BIG = 512 * 1024, SMALL = 512 * 64;
    int idx = blockIdx.x * 256 + threadIdx.x;
    const float* W; uint32_t *Wh, *Wl; int i, N;
    if (idx < BIG)               { W = Wq; Wh = wqh; Wl = wql; i = idx;            N = 1024; }
    else if (idx < 2 * BIG)      { W = Wo; Wh = woh; Wl = wol; i = idx - BIG;      N = 1024; }
    else if (idx < 2 * BIG + SMALL) { W = Wk; Wh = wkh; Wl = wkl; i = idx - 2*BIG; N = 64; }
    else if (idx < 2 * BIG + 2 * SMALL) { W = Wv; Wh = wvh; Wl = wvl; i = idx - 2*BIG - SMALL; N = 64; }
    else return;
    int kp = i / N, n = i - kp * N;
    float a = W[(size_t)(2 * kp) * N + n];
    float b = W[(size_t)(2 * kp + 1) * N + n];
    uint32_t h, l;
    split2(a, b, h, l);
    Wh[i] = h; Wl[i] = l;
}

// ---------------- bf16x3 GEMM + bias, pre-split B ---------------------------
// CMODE 0: C fp32. CMODE 1: packed dk-pair epilogue -> Ch/Cl [M][N/2].
// CMODE 3: fused K/V projection — blockIdx.x selects matrix:
//          0 -> K-style epilogue (args 1), 1 -> V-transposed epilogue (args 2).
template<int BM, int BN, int BK, int WARPS_M, int WARPS_N, int CMODE>
__global__ __launch_bounds__(WARPS_M * WARPS_N * 32)
void bgemm3(const float* __restrict__ A, const uint32_t* __restrict__ Bh,
            const uint32_t* __restrict__ Bl, const float* __restrict__ bias,
            float* __restrict__ C, uint32_t* __restrict__ Ch,
            uint32_t* __restrict__ Cl,
            const float* __restrict__ A2, const uint32_t* __restrict__ Bh2,
            const uint32_t* __restrict__ Bl2, const float* __restrict__ bias2,
            uint32_t* __restrict__ Ch2, uint32_t* __restrict__ Cl2,
            int M, int N, int K)
{
    constexpr int THREADS = WARPS_M * WARPS_N * 32;
    constexpr int WM = BM / WARPS_M, WN = BN / WARPS_N;
    constexpr int MT = WM / 16, NT = WN / 8;
    constexpr int KW = BK / 2;
    constexpr int AW = KW + 4;
    constexpr int BW = BN + 8;
    constexpr int A_IT = BM * BK / (4 * THREADS);
    constexpr int B_IT = KW * (BN / 4) / THREADS;

    __shared__ uint32_t Ash[BM][AW], Asl[BM][AW];
    __shared__ uint32_t Bsh[KW][BW], Bsl[KW][BW];

    bool isV = false;
    if constexpr (CMODE == 3) {
        if (blockIdx.x == 1) {
            isV = true;
            A = A2; Bh = Bh2; Bl = Bl2; bias = bias2; Ch = Ch2; Cl = Cl2;
        }
    }

    const int tid  = threadIdx.x;
    const int warp = tid >> 5, lane = tid & 31;
    const int g = lane >> 2, q = lane & 3;
    const int wm = warp / WARPS_N, wn = warp % WARPS_N;
    const int m0 = blockIdx.y * BM;
    const int n0 = (CMODE == 3) ? 0 : blockIdx.x * BN;

    float acc[MT][NT][4];
    #pragma unroll
    for (int i = 0; i < MT; i++)
        #pragma unroll
        for (int j = 0; j < NT; j++)
            #pragma unroll
            for (int e = 0; e < 4; e++) acc[i][j][e] = 0.f;

    float4 aPF[A_IT];
    uint4  bPFh[B_IT], bPFl[B_IT];

    auto loadT = [&](int k0) {
        #pragma unroll
        for (int i = 0; i < A_IT; i++) {
            int flat = tid + i * THREADS;
            int r = flat / (BK / 4), c = (flat % (BK / 4)) * 4;
            aPF[i] = *(const float4*)(A + (size_t)(m0 + r) * K + k0 + c);
        }
        int kp0 = k0 / 2;
        #pragma unroll
        for (int i = 0; i < B_IT; i++) {
            int flat = tid + i * THREADS;
            int kp2 = flat / (BN / 4), c = (flat % (BN / 4)) * 4;
            bPFh[i] = *(const uint4*)(Bh + (size_t)(kp0 + kp2) * N + n0 + c);
            bPFl[i] = *(const uint4*)(Bl + (size_t)(kp0 + kp2) * N + n0 + c);
        }
    };
    auto storeT = [&]() {
        #pragma unroll
        for (int i = 0; i < A_IT; i++) {
            int flat = tid + i * THREADS;
            int r = flat / (BK / 4), c = (flat % (BK / 4)) * 4;
            uint32_t h0, l0, h1, l1;
            split2(aPF[i].x, aPF[i].y, h0, l0);
            split2(aPF[i].z, aPF[i].w, h1, l1);
            Ash[r][c / 2] = h0; Ash[r][c / 2 + 1] = h1;
            Asl[r][c / 2] = l0; Asl[r][c / 2 + 1] = l1;
        }
        #pragma unroll
        for (int i = 0; i < B_IT; i++) {
            int flat = tid + i * THREADS;
            int kp2 = flat / (BN / 4), c = (flat % (BN / 4)) * 4;
            *(uint4*)&Bsh[kp2][c] = bPFh[i];
            *(uint4*)&Bsl[kp2][c] = bPFl[i];
        }
    };

    loadT(0);
    for (int k0 = 0; k0 < K; k0 += BK) {
        __syncthreads();
        storeT();
        __syncthreads();
        if (k0 + BK < K) loadT(k0 + BK);

        #pragma unroll
        for (int kk = 0; kk < 2; kk++) {
            const int wof = kk * 8;
            uint32_t Ah[MT][4], Al[MT][4], Bfh[NT][2], Bfl[NT][2];
            #pragma unroll
            for (int i = 0; i < MT; i++) {
                int mr = wm * WM + i * 16;
                Ah[i][0] = Ash[mr + g][wof + q];
                Ah[i][1] = Ash[mr + g + 8][wof + q];
                Ah[i][2] = Ash[mr + g][wof + q + 4];
                Ah[i][3] = Ash[mr + g + 8][wof + q + 4];
                Al[i][0] = Asl[mr + g][wof + q];
                Al[i][1] = Asl[mr + g + 8][wof + q];
                Al[i][2] = Asl[mr + g][wof + q + 4];
                Al[i][3] = Asl[mr + g + 8][wof + q + 4];
            }
            #pragma unroll
            for (int j = 0; j < NT; j++) {
                int nc = wn * WN + j * 8 + g;
                Bfh[j][0] = Bsh[wof + q][nc];
                Bfh[j][1] = Bsh[wof + q + 4][nc];
                Bfl[j][0] = Bsl[wof + q][nc];
                Bfl[j][1] = Bsl[wof + q + 4][nc];
            }
            #pragma unroll
            for (int i = 0; i < MT; i++)
                #pragma unroll
                for (int j = 0; j < NT; j++)
                    mma_bf16(acc[i][j], Ah[i], Bfh[j][0], Bfh[j][1]);
            #pragma unroll
            for (int i = 0; i < MT; i++)
                #pragma unroll
                for (int j = 0; j < NT; j++)
                    mma_bf16(acc[i][j], Ah[i], Bfl[j][0], Bfl[j][1]);
            #pragma unroll
            for (int i = 0; i < MT; i++)
                #pragma unroll
                for (int j = 0; j < NT; j++)
                    mma_bf16(acc[i][j], Al[i], Bfh[j][0], Bfh[j][1]);
        }
    }

    const unsigned FULL = 0xffffffffu;
    #pragma unroll
    for (int i = 0; i < MT; i++) {
        int row0 = m0 + wm * WM + i * 16 + g;
        #pragma unroll
        for (int j = 0; j < NT; j++) {
            int col = n0 + wn * WN + j * 8 + 2 * q;
            float bx = bias[col], by = bias[col + 1];
            float v0 = acc[i][j][0] + bx, v1 = acc[i][j][1] + by;
            float v2 = acc[i][j][2] + bx, v3 = acc[i][j][3] + by;
            if constexpr (CMODE == 0) {
                float2 w0 = { v0, v1 }, w1 = { v2, v3 };
                *(float2*)(C + (size_t)row0 * N + col) = w0;
                *(float2*)(C + (size_t)(row0 + 8) * N + col) = w1;
            } else {
                bool kstyle = (CMODE == 1) || !isV;
                if (kstyle) {
                    uint32_t h, l;
                    split2(v0, v1, h, l);
                    Ch[(size_t)row0 * (N / 2) + col / 2] = h;
                    Cl[(size_t)row0 * (N / 2) + col / 2] = l;
                    split2(v2, v3, h, l);
                    Ch[(size_t)(row0 + 8) * (N / 2) + col / 2] = h;
                    Cl[(size_t)(row0 + 8) * (N / 2) + col / 2] = l;
                } else {
                    float p0 = __shfl_xor_sync(FULL, v0, 4);
                    float p1 = __shfl_xor_sync(FULL, v1, 4);
                    float p2 = __shfl_xor_sync(FULL, v2, 4);
                    float p3 = __shfl_xor_sync(FULL, v3, 4);
                    uint32_t h, l;
                    if ((g & 1) == 0) {
                        split2(v0, p0, h, l);
                        Ch[(size_t)col * (S_LEN / 2) + row0 / 2] = h;
                        Cl[(size_t)col * (S_LEN / 2) + row0 / 2] = l;
                        split2(v2, p2, h, l);
                        Ch[(size_t)col * (S_LEN / 2) + (row0 + 8) / 2] = h;
                        Cl[(size_t)col * (S_LEN / 2) + (row0 + 8) / 2] = l;
                    } else {
                        split2(p1, v1, h, l);
                        Ch[(size_t)(col + 1) * (S_LEN / 2) + (row0 - 1) / 2] = h;
                        Cl[(size_t)(col + 1) * (S_LEN / 2) + (row0 - 1) / 2] = l;
                        split2(p3, v3, h, l);
                        Ch[(size_t)(col + 1) * (S_LEN / 2) + (row0 + 7) / 2] = h;
                        Cl[(size_t)(col + 1) * (S_LEN / 2) + (row0 + 7) / 2] = l;
                    }
                }
            }
        }
    }
}

// ---------------- flash MQA attention (cp.async + LDSM, 2 CTAs/SM) ----------
// smem: 2 buffers x [KH 9216 | KL 9216 | VH 9216 | VL 9216]; Q staged in buf1.
#define PW   36
#define BUFB 36864
#define QH_OFF 36864
#define QL_OFF 55296
#define ATTN_SMEM 73728

__global__ __launch_bounds__(256, 2)
void mqa_attn_a(const uint32_t* __restrict__ qph, const uint32_t* __restrict__ qpl,
                const uint32_t* __restrict__ kph, const uint32_t* __restrict__ kpl,
                const uint32_t* __restrict__ vth, const uint32_t* __restrict__ vtl,
                float* __restrict__ out)
{
    extern __shared__ char smraw[];
    const uint32_t smb = smem_u32(smraw);
    const int tid  = threadIdx.x;
    const int warp = tid >> 5, lane = tid & 31;
    const int gl = lane >> 2, q = lane & 3;
    const int lt = lane >> 3, lr = lane & 7;   // ldmatrix addr mapping
    const int head = blockIdx.y;
    const int q0 = blockIdx.x * 128;
    const unsigned FULL = 0xffffffffu;

    // ---- stage packed Q into buf1 ----
    #pragma unroll
    for (int i = 0; i < 4; i++) {
        int idx = tid + i * 256;
        int r = idx >> 3, c4 = (idx & 7) * 4;
        *(uint4*)(smraw + QH_OFF + (r * PW + c4) * 4) =
            *(const uint4*)(qph + (size_t)(q0 + r) * 512 + head * 32 + c4);
        *(uint4*)(smraw + QL_OFF + (r * PW + c4) * 4) =
            *(const uint4*)(qpl + (size_t)(q0 + r) * 512 + head * 32 + c4);
    }

    // ---- async K/V chunk load ----
    const int kkey = tid >> 2, kw0 = (tid & 3) * 8;
    auto loadKV = [&](int k0, int bb) {
        uint32_t base = smb + (uint32_t)bb + (kkey * PW + kw0) * 4;
        const uint32_t* ph = kph + (size_t)(k0 + kkey) * 32 + kw0;
        const uint32_t* pl = kpl + (size_t)(k0 + kkey) * 32 + kw0;
        cp16(base,             ph);
        cp16(base + 16,        ph + 4);
        cp16(base + 9216,      pl);
        cp16(base + 9216 + 16, pl + 4);
        const uint32_t* vh = vth + (size_t)kkey * (S_LEN / 2) + (k0 >> 1) + kw0;
        const uint32_t* vl = vtl + (size_t)kkey * (S_LEN / 2) + (k0 >> 1) + kw0;
        cp16(base + 18432,      vh);
        cp16(base + 18432 + 16, vh + 4);
        cp16(base + 27648,      vl);
        cp16(base + 27648 + 16, vl + 4);
        CP_COMMIT();
    };

    loadKV(0, 0);
    __syncthreads();   // Q stores visible

    // ---- Q fragments via ldmatrix ----
    uint32_t Qh[4][4], Ql[4][4];
    {
        uint32_t brow = (uint32_t)(warp * 16 + 8 * (lt & 1) + lr);
        #pragma unroll
        for (int s = 0; s < 4; s++) {
            uint32_t aoff = (brow * PW + 8 * s + 4 * (lt >> 1)) * 4;
            ldsm4(Qh[s][0], Qh[s][1], Qh[s][2], Qh[s][3], smb + QH_OFF + aoff);
            ldsm4(Ql[s][0], Ql[s][1], Ql[s][2], Ql[s][3], smb + QL_OFF + aoff);
        }
    }
    CP_WAIT0();
    __syncthreads();   // buf0 ready; all warps done reading Q region

    float O[8][4];
    #pragma unroll
    for (int j = 0; j < 8; j++)
        #pragma unroll
        for (int e = 0; e < 4; e++) O[j][e] = 0.f;
    float ls0 = 0.f, ls1 = 0.f;

    for (int ci = 0; ci < S_LEN / 64; ci++) {
        const int bb = (ci & 1) * BUFB;
        if (ci < S_LEN / 64 - 1) loadKV((ci + 1) * 64, bb ^ BUFB);

        #pragma unroll
        for (int g = 0; g < 4; g++) {
            // ---- S = Q K^T for 16 keys (2 j-tiles, 2 accumulation chains) --
            uint32_t kh[2][8], kl[2][8];
            uint32_t krow = (uint32_t)(16 * g + 8 * (lt >> 1) + lr);
            #pragma unroll
            for (int s = 0; s < 4; s++) {
                uint32_t aoff = (krow * PW + 8 * s + 4 * (lt & 1)) * 4;
                ldsm4(kh[0][2*s], kh[0][2*s+1], kh[1][2*s], kh[1][2*s+1],
                      smb + bb + aoff);
                ldsm4(kl[0][2*s], kl[0][2*s+1], kl[1][2*s], kl[1][2*s+1],
                      smb + bb + 9216 + aoff);
            }
            float Sf[2][2][4];
            #pragma unroll
            for (int jj = 0; jj < 2; jj++)
                #pragma unroll
                for (int ch = 0; ch < 2; ch++)
                    #pragma unroll
                    for (int e = 0; e < 4; e++) Sf[jj][ch][e] = 0.f;
            #pragma unroll
            for (int s = 0; s < 4; s++)
                #pragma unroll
                for (int jj = 0; jj < 2; jj++)
                    mma_bf16(Sf[jj][s & 1], Qh[s], kh[jj][2 * s], kh[jj][2 * s + 1]);
            #pragma unroll
            for (int s = 0; s < 4; s++)
                #pragma unroll
                for (int jj = 0; jj < 2; jj++)
                    mma_bf16(Sf[jj][s & 1], Qh[s], kl[jj][2 * s], kl[jj][2 * s + 1]);
            #pragma unroll
            for (int s = 0; s < 4; s++)
                #pragma unroll
                for (int jj = 0; jj < 2; jj++)
                    mma_bf16(Sf[jj][s & 1], Ql[s], kh[jj][2 * s], kh[jj][2 * s + 1]);

            // ---- P = exp(S), row sums, pack ----
            float ev[2][4];
            #pragma unroll
            for (int jj = 0; jj < 2; jj++)
                #pragma unroll
                for (int e = 0; e < 4; e++)
                    ev[jj][e] = __expf(Sf[jj][0][e] + Sf[jj][1][e]);
            #pragma unroll
            for (int jj = 0; jj < 2; jj++) {
                ls0 += ev[jj][0] + ev[jj][1];
                ls1 += ev[jj][2] + ev[jj][3];
            }
            uint32_t Ph[4], Pl[4];
            split2(ev[0][0], ev[0][1], Ph[0], Pl[0]);
            split2(ev[0][2], ev[0][3], Ph[1], Pl[1]);
            split2(ev[1][0], ev[1][1], Ph[2], Pl[2]);
            split2(ev[1][2], ev[1][3], Ph[3], Pl[3]);

            // ---- O += P V ----
            uint32_t vh[16], vl[16];
            #pragma unroll
            for (int c = 0; c < 4; c++) {
                uint32_t vrow = (uint32_t)(8 * (2 * c + (lt >> 1)) + lr);
                uint32_t aoff = (vrow * PW + 8 * g + 4 * (lt & 1)) * 4;
                ldsm4(vh[4*c], vh[4*c+1], vh[4*c+2], vh[4*c+3],
                      smb + bb + 18432 + aoff);
                ldsm4(vl[4*c], vl[4*c+1], vl[4*c+2], vl[4*c+3],
                      smb + bb + 27648 + aoff);
            }
            #pragma unroll
            for (int jv = 0; jv < 8; jv++) mma_bf16(O[jv], Ph, vh[2 * jv], vh[2 * jv + 1]);
            #pragma unroll
            for (int jv = 0; jv < 8; jv++) mma_bf16(O[jv], Ph, vl[2 * jv], vl[2 * jv + 1]);
            #pragma unroll
            for (int jv = 0; jv < 8; jv++) mma_bf16(O[jv], Pl, vh[2 * jv], vh[2 * jv + 1]);
        }

        CP_WAIT0();
        __syncthreads();
    }

    // final row-sum reduction and write
    ls0 += __shfl_xor_sync(FULL, ls0, 1);
    ls0 += __shfl_xor_sync(FULL, ls0, 2);
    ls1 += __shfl_xor_sync(FULL, ls1, 1);
    ls1 += __shfl_xor_sync(FULL, ls1, 2);
    float inv0 = 1.f / ls0, inv1 = 1.f / ls1;
    int row0 = q0 + warp * 16 + gl;
    #pragma unroll
    for (int j = 0; j < 8; j++) {
        int col = head * DKV + j * 8 + 2 * q;
        float2 w0 = { O[j][0] * inv0, O[j][1] * inv0 };
        float2 w1 = { O[j][2] * inv1, O[j][3] * inv1 };
        *(float2*)(out + (size_t)row0 * DMODEL + col) = w0;
        *(float2*)(out + (size_t)(row0 + 8) * DMODEL + col) = w1;
    }
}

// ---------------- launch ----------------------------------------------------
extern "C" void kernel_launch(void* const* d_in, const int* in_sizes, int n_in,
                              void* d_out, int out_size)
{
    const float* q  = (const float*)d_in[0];
    const float* k  = (const float*)d_in[1];
    const float* v  = (const float*)d_in[2];
    const float* Wq = (const float*)d_in[3];
    const float* bq = (const float*)d_in[4];
    const float* Wk = (const float*)d_in[5];
    const float* bk = (const float*)d_in[6];
    const float* Wv = (const float*)d_in[7];
    const float* bv = (const float*)d_in[8];
    const float* Wo = (const float*)d_in[9];
    const float* bo = (const float*)d_in[10];
    float* out = (float*)d_out;

    void* p;
    cudaGetSymbolAddress(&p, g_att);  float* att = (float*)p;
    cudaGetSymbolAddress(&p, g_wqh);  uint32_t* wqh = (uint32_t*)p;
    cudaGetSymbolAddress(&p, g_wql);  uint32_t* wql = (uint32_t*)p;
    cudaGetSymbolAddress(&p, g_wkh);  uint32_t* wkh = (uint32_t*)p;
    cudaGetSymbolAddress(&p, g_wkl);  uint32_t* wkl = (uint32_t*)p;
    cudaGetSymbolAddress(&p, g_wvh);  uint32_t* wvh = (uint32_t*)p;
    cudaGetSymbolAddress(&p, g_wvl);  uint32_t* wvl = (uint32_t*)p;
    cudaGetSymbolAddress(&p, g_woh);  uint32_t* woh = (uint32_t*)p;
    cudaGetSymbolAddress(&p, g_wol);  uint32_t* wol = (uint32_t*)p;
    cudaGetSymbolAddress(&p, g_qph);  uint32_t* qph = (uint32_t*)p;
    cudaGetSymbolAddress(&p, g_qpl);  uint32_t* qpl = (uint32_t*)p;
    cudaGetSymbolAddress(&p, g_kph);  uint32_t* kph = (uint32_t*)p;
    cudaGetSymbolAddress(&p, g_kpl);  uint32_t* kpl = (uint32_t*)p;
    cudaGetSymbolAddress(&p, g_vth);  uint32_t* vth = (uint32_t*)p;
    cudaGetSymbolAddress(&p, g_vtl);  uint32_t* vtl = (uint32_t*)p;

    cudaFuncSetAttribute((const void*)mqa_attn_a,
                         cudaFuncAttributeMaxDynamicSharedMemorySize, ATTN_SMEM);

    // weight pre-split (one launch)
    splitAll<<<(2 * 512 * 1024 + 2 * 512 * 64 + 255) / 256, 256>>>(
        Wq, Wo, Wk, Wv, wqh, wql, woh, wol, wkh, wkl, wvh, wvl);

    // Q projection (packed epilogue)
    bgemm3<128, 128, 32, 2, 4, 1>
        <<<dim3(DMODEL / 128, S_LEN / 128), 256>>>(q, wqh, wql, bq, nullptr,
                                                   qph, qpl,
                                                   nullptr, nullptr, nullptr,
                                                   nullptr, nullptr, nullptr,
                                                   S_LEN, DMODEL, DMODEL);
    // K + V projections fused (128 CTAs)
    bgemm3<64, 64, 32, 2, 4, 3>
        <<<dim3(2, S_LEN / 64), 256>>>(k, wkh, wkl, bk, nullptr, kph, kpl,
                                       v, wvh, wvl, bv, vth, vtl,
                                       S_LEN, DKV, DMODEL);
    // attention
    mqa_attn_a<<<dim3(S_LEN / 128, HEADS), 256, ATTN_SMEM>>>(qph, qpl, kph, kpl,
                                                             vth, vtl, att);
    // O projection
    bgemm3<128, 128, 32, 2, 4, 0>
        <<<dim3(DMODEL / 128, S_LEN / 128), 256>>>(att, woh, wol, bo, out,
                                                   nullptr, nullptr,
                                                   nullptr, nullptr, nullptr,
                                                   nullptr, nullptr, nullptr,
                                                   S_LEN, DMODEL, DMODEL);
}

// round 10
// speedup vs baseline: 1.0552x; 1.0552x over previous
#include <cuda_runtime.h>
#include <cstdint>

#define S_LEN   4096
#define DMODEL  1024
#define HEADS   16
#define DKV     64

// ---------------- scratch ---------------------------------------------------
__device__ float    g_att[S_LEN * DMODEL];       // fp32 [s, h*64+d]
__device__ uint32_t g_wqh[512 * 1024], g_wql[512 * 1024];
__device__ uint32_t g_wkh[512 * 64],   g_wkl[512 * 64];
__device__ uint32_t g_wvh[512 * 64],   g_wvl[512 * 64];
__device__ uint32_t g_woh[512 * 1024], g_wol[512 * 1024];
__device__ uint32_t g_qph[S_LEN * 512], g_qpl[S_LEN * 512];   // [s][dk-pair of dmodel]
__device__ uint32_t g_kph[S_LEN * 32], g_kpl[S_LEN * 32];     // [key][dk-pair]
__device__ uint32_t g_vth[64 * (S_LEN / 2)], g_vtl[64 * (S_LEN / 2)]; // [dk][key-pair]

// ---------------- bf16 helpers ----------------------------------------------
__device__ __forceinline__ void split2(float x, float y, uint32_t& h, uint32_t& l) {
    uint32_t hp;
    asm("cvt.rn.bf16x2.f32 %0,%1,%2;" : "=r"(hp) : "f"(y), "f"(x));
    float hx = __uint_as_float(hp << 16);
    float hy = __uint_as_float(hp & 0xffff0000u);
    asm("cvt.rn.bf16x2.f32 %0,%1,%2;" : "=r"(l) : "f"(y - hy), "f"(x - hx));
    h = hp;
}
__device__ __forceinline__ void mma_bf16(float* d, const uint32_t* a,
                                         uint32_t b0, uint32_t b1) {
    asm volatile("mma.sync.aligned.m16n8k16.row.col.f32.bf16.bf16.f32 "
        "{%0,%1,%2,%3},{%4,%5,%6,%7},{%8,%9},{%0,%1,%2,%3};"
        : "+f"(d[0]), "+f"(d[1]), "+f"(d[2]), "+f"(d[3])
        : "r"(a[0]), "r"(a[1]), "r"(a[2]), "r"(a[3]), "r"(b0), "r"(b1));
}
__device__ __forceinline__ void ldsm4(uint32_t& r0, uint32_t& r1,
                                      uint32_t& r2, uint32_t& r3, uint32_t addr) {
    asm volatile("ldmatrix.sync.aligned.m8n8.x4.shared.b16 {%0,%1,%2,%3}, [%4];"
                 : "=r"(r0), "=r"(r1), "=r"(r2), "=r"(r3) : "r"(addr));
}
__device__ __forceinline__ uint32_t smem_u32(const void* p) {
    uint32_t a;
    asm("{ .reg .u64 t; cvta.to.shared.u64 t, %1; cvt.u32.u64 %0, t; }"
        : "=r"(a) : "l"(p));
    return a;
}
__device__ __forceinline__ void cp16(uint32_t saddr, const void* g) {
    asm volatile("cp.async.cg.shared.global [%0], [%1], 16;" :: "r"(saddr), "l"(g));
}
#define CP_COMMIT() asm volatile("cp.async.commit_group;" ::: "memory")
#define CP_WAIT0()  asm volatile("cp.async.wait_group 0;"  ::: "memory")

// ---------------- combined weight pre-split ---------------------------------
__global__ __launch_bounds__(256)
void splitAll(const float* __restrict__ Wq, const float* __restrict__ Wo,
              const float* __restrict__ Wk, const float* __restrict__ Wv,
              uint32_t* __restrict__ wqh, uint32_t* __restrict__ wql,
              uint32_t* __restrict__ woh, uint32_t* __restrict__ wol,
              uint32_t* __restrict__ wkh, uint32_t* __restrict__ wkl,
              uint32_t* __restrict__ wvh, uint32_t* __restrict__ wvl)
{
    constexpr int BIG = 512 * 1024, SMALL = 512 * 64;
    int idx = blockIdx.x * 256 + threadIdx.x;
    const float* W; uint32_t *Wh, *Wl; int i, N;
    if (idx < BIG)               { W = Wq; Wh = wqh; Wl = wql; i = idx;            N = 1024; }
    else if (idx < 2 * BIG)      { W = Wo; Wh = woh; Wl = wol; i = idx - BIG;      N = 1024; }
    else if (idx < 2 * BIG + SMALL) { W = Wk; Wh = wkh; Wl = wkl; i = idx - 2*BIG; N = 64; }
    else if (idx < 2 * BIG + 2 * SMALL) { W = Wv; Wh = wvh; Wl = wvl; i = idx - 2*BIG - SMALL; N = 64; }
    else return;
    int kp = i / N, n = i - kp * N;
    float a = W[(size_t)(2 * kp) * N + n];
    float b = W[(size_t)(2 * kp + 1) * N + n];
    uint32_t h, l;
    split2(a, b, h, l);
    Wh[i] = h; Wl[i] = l;
}

// ---------------- bf16x3 GEMM, cp.async double-buffered ---------------------
// CMODE 0: C fp32. CMODE 1: packed dk-pair epilogue -> Ch/Cl [M][N/2].
// CMODE 3: fused K/V projection — blockIdx.x 0 = K-style, 1 = V-transposed.
template<int BM, int BN, int BK, int WARPS_M, int WARPS_N, int CMODE>
__global__ __launch_bounds__(WARPS_M * WARPS_N * 32)
void bgemm3(const float* __restrict__ A, const uint32_t* __restrict__ Bh,
            const uint32_t* __restrict__ Bl, const float* __restrict__ bias,
            float* __restrict__ C, uint32_t* __restrict__ Ch,
            uint32_t* __restrict__ Cl,
            const float* __restrict__ A2, const uint32_t* __restrict__ Bh2,
            const uint32_t* __restrict__ Bl2, const float* __restrict__ bias2,
            uint32_t* __restrict__ Ch2, uint32_t* __restrict__ Cl2,
            int M, int N, int K)
{
    constexpr int THREADS = WARPS_M * WARPS_N * 32;
    constexpr int WM = BM / WARPS_M, WN = BN / WARPS_N;
    constexpr int MT = WM / 16, NT = WN / 8;
    constexpr int KW = BK / 2;
    constexpr int AW = KW + 4;
    constexpr int BW = BN + 8;
    constexpr int ASZ = BM * AW;      // words per A buffer
    constexpr int BSZ = KW * BW;      // words per B buffer
    constexpr int A_IT = BM * BK / (4 * THREADS);
    constexpr int B_IT = KW * (BN / 4) / THREADS;

    extern __shared__ uint32_t smw[];
    uint32_t* AshB = smw;                       // [2][ASZ]
    uint32_t* AslB = smw + 2 * ASZ;
    uint32_t* BshB = smw + 4 * ASZ;             // [2][BSZ]
    uint32_t* BslB = smw + 4 * ASZ + 2 * BSZ;
    const uint32_t sm_bsh = smem_u32(BshB);
    const uint32_t sm_bsl = smem_u32(BslB);

    bool isV = false;
    if constexpr (CMODE == 3) {
        if (blockIdx.x == 1) {
            isV = true;
            A = A2; Bh = Bh2; Bl = Bl2; bias = bias2; Ch = Ch2; Cl = Cl2;
        }
    }

    const int tid  = threadIdx.x;
    const int warp = tid >> 5, lane = tid & 31;
    const int g = lane >> 2, q = lane & 3;
    const int wm = warp / WARPS_N, wn = warp % WARPS_N;
    const int m0 = blockIdx.y * BM;
    const int n0 = (CMODE == 3) ? 0 : blockIdx.x * BN;

    float acc[MT][NT][4];
    #pragma unroll
    for (int i = 0; i < MT; i++)
        #pragma unroll
        for (int j = 0; j < NT; j++)
            #pragma unroll
            for (int e = 0; e < 4; e++) acc[i][j][e] = 0.f;

    float4 aPF[A_IT];

    auto loadA = [&](int k0) {
        #pragma unroll
        for (int i = 0; i < A_IT; i++) {
            int flat = tid + i * THREADS;
            int r = flat / (BK / 4), c = (flat % (BK / 4)) * 4;
            aPF[i] = *(const float4*)(A + (size_t)(m0 + r) * K + k0 + c);
        }
    };
    auto cpB = [&](int k0, int b) {
        int kp0 = k0 / 2;
        #pragma unroll
        for (int i = 0; i < B_IT; i++) {
            int flat = tid + i * THREADS;
            int kp2 = flat / (BN / 4), c = (flat % (BN / 4)) * 4;
            uint32_t off = (uint32_t)((b * BSZ + kp2 * BW + c) * 4);
            cp16(sm_bsh + off, Bh + (size_t)(kp0 + kp2) * N + n0 + c);
            cp16(sm_bsl + off, Bl + (size_t)(kp0 + kp2) * N + n0 + c);
        }
        CP_COMMIT();
    };
    auto storeA = [&](int b) {
        uint32_t* Ash = AshB + b * ASZ;
        uint32_t* Asl = AslB + b * ASZ;
        #pragma unroll
        for (int i = 0; i < A_IT; i++) {
            int flat = tid + i * THREADS;
            int r = flat / (BK / 4), c = (flat % (BK / 4)) * 4;
            uint32_t h0, l0, h1, l1;
            split2(aPF[i].x, aPF[i].y, h0, l0);
            split2(aPF[i].z, aPF[i].w, h1, l1);
            Ash[r * AW + c / 2] = h0; Ash[r * AW + c / 2 + 1] = h1;
            Asl[r * AW + c / 2] = l0; Asl[r * AW + c / 2 + 1] = l1;
        }
    };

    // prologue: fill buffer 0
    loadA(0);
    cpB(0, 0);
    storeA(0);
    CP_WAIT0();
    __syncthreads();

    for (int k0 = 0; k0 < K; k0 += BK) {
        const int b = (k0 / BK) & 1;
        const bool more = (k0 + BK < K);
        if (more) { loadA(k0 + BK); cpB(k0 + BK, b ^ 1); }

        const uint32_t* Ash = AshB + b * ASZ;
        const uint32_t* Asl = AslB + b * ASZ;
        const uint32_t* Bsh = BshB + b * BSZ;
        const uint32_t* Bsl = BslB + b * BSZ;

        #pragma unroll
        for (int kk = 0; kk < 2; kk++) {
            const int wof = kk * 8;
            uint32_t Ah[MT][4], Al[MT][4], Bfh[NT][2], Bfl[NT][2];
            #pragma unroll
            for (int i = 0; i < MT; i++) {
                int mr = wm * WM + i * 16;
                Ah[i][0] = Ash[(mr + g) * AW + wof + q];
                Ah[i][1] = Ash[(mr + g + 8) * AW + wof + q];
                Ah[i][2] = Ash[(mr + g) * AW + wof + q + 4];
                Ah[i][3] = Ash[(mr + g + 8) * AW + wof + q + 4];
                Al[i][0] = Asl[(mr + g) * AW + wof + q];
                Al[i][1] = Asl[(mr + g + 8) * AW + wof + q];
                Al[i][2] = Asl[(mr + g) * AW + wof + q + 4];
                Al[i][3] = Asl[(mr + g + 8) * AW + wof + q + 4];
            }
            #pragma unroll
            for (int j = 0; j < NT; j++) {
                int nc = wn * WN + j * 8 + g;
                Bfh[j][0] = Bsh[(wof + q) * BW + nc];
                Bfh[j][1] = Bsh[(wof + q + 4) * BW + nc];
                Bfl[j][0] = Bsl[(wof + q) * BW + nc];
                Bfl[j][1] = Bsl[(wof + q + 4) * BW + nc];
            }
            #pragma unroll
            for (int i = 0; i < MT; i++)
                #pragma unroll
                for (int j = 0; j < NT; j++)
                    mma_bf16(acc[i][j], Ah[i], Bfh[j][0], Bfh[j][1]);
            #pragma unroll
            for (int i = 0; i < MT; i++)
                #pragma unroll
                for (int j = 0; j < NT; j++)
                    mma_bf16(acc[i][j], Ah[i], Bfl[j][0], Bfl[j][1]);
            #pragma unroll
            for (int i = 0; i < MT; i++)
                #pragma unroll
                for (int j = 0; j < NT; j++)
                    mma_bf16(acc[i][j], Al[i], Bfh[j][0], Bfh[j][1]);
        }

        if (more) storeA(b ^ 1);
        CP_WAIT0();
        __syncthreads();
    }

    const unsigned FULL = 0xffffffffu;
    #pragma unroll
    for (int i = 0; i < MT; i++) {
        int row0 = m0 + wm * WM + i * 16 + g;
        #pragma unroll
        for (int j = 0; j < NT; j++) {
            int col = n0 + wn * WN + j * 8 + 2 * q;
            float bx = bias[col], by = bias[col + 1];
            float v0 = acc[i][j][0] + bx, v1 = acc[i][j][1] + by;
            float v2 = acc[i][j][2] + bx, v3 = acc[i][j][3] + by;
            if constexpr (CMODE == 0) {
                float2 w0 = { v0, v1 }, w1 = { v2, v3 };
                *(float2*)(C + (size_t)row0 * N + col) = w0;
                *(float2*)(C + (size_t)(row0 + 8) * N + col) = w1;
            } else {
                bool kstyle = (CMODE == 1) || !isV;
                if (kstyle) {
                    uint32_t h, l;
                    split2(v0, v1, h, l);
                    Ch[(size_t)row0 * (N / 2) + col / 2] = h;
                    Cl[(size_t)row0 * (N / 2) + col / 2] = l;
                    split2(v2, v3, h, l);
                    Ch[(size_t)(row0 + 8) * (N / 2) + col / 2] = h;
                    Cl[(size_t)(row0 + 8) * (N / 2) + col / 2] = l;
                } else {
                    float p0 = __shfl_xor_sync(FULL, v0, 4);
                    float p1 = __shfl_xor_sync(FULL, v1, 4);
                    float p2 = __shfl_xor_sync(FULL, v2, 4);
                    float p3 = __shfl_xor_sync(FULL, v3, 4);
                    uint32_t h, l;
                    if ((g & 1) == 0) {
                        split2(v0, p0, h, l);
                        Ch[(size_t)col * (S_LEN / 2) + row0 / 2] = h;
                        Cl[(size_t)col * (S_LEN / 2) + row0 / 2] = l;
                        split2(v2, p2, h, l);
                        Ch[(size_t)col * (S_LEN / 2) + (row0 + 8) / 2] = h;
                        Cl[(size_t)col * (S_LEN / 2) + (row0 + 8) / 2] = l;
                    } else {
                        split2(p1, v1, h, l);
                        Ch[(size_t)(col + 1) * (S_LEN / 2) + (row0 - 1) / 2] = h;
                        Cl[(size_t)(col + 1) * (S_LEN / 2) + (row0 - 1) / 2] = l;
                        split2(p3, v3, h, l);
                        Ch[(size_t)(col + 1) * (S_LEN / 2) + (row0 + 7) / 2] = h;
                        Cl[(size_t)(col + 1) * (S_LEN / 2) + (row0 + 7) / 2] = l;
                    }
                }
            }
        }
    }
}

// ---------------- flash MQA attention (cp.async + LDSM + 2-slot pipeline) ---
// smem: 2 buffers x [KH 9216 | KL 9216 | VH 9216 | VL 9216]; Q staged in buf1.
#define PW   36
#define BUFB 36864
#define QH_OFF 36864
#define QL_OFF 55296
#define ATTN_SMEM 73728

__global__ __launch_bounds__(256, 2)
void mqa_attn_b(const uint32_t* __restrict__ qph, const uint32_t* __restrict__ qpl,
                const uint32_t* __restrict__ kph, const uint32_t* __restrict__ kpl,
                const uint32_t* __restrict__ vth, const uint32_t* __restrict__ vtl,
                float* __restrict__ out)
{
    extern __shared__ char smraw[];
    const uint32_t smb = smem_u32(smraw);
    const int tid  = threadIdx.x;
    const int warp = tid >> 5, lane = tid & 31;
    const int gl = lane >> 2, q = lane & 3;
    const int lt = lane >> 3, lr = lane & 7;   // ldmatrix addr mapping
    const int head = blockIdx.y;
    const int q0 = blockIdx.x * 128;
    const unsigned FULL = 0xffffffffu;

    // ---- stage packed Q into buf1 ----
    #pragma unroll
    for (int i = 0; i < 4; i++) {
        int idx = tid + i * 256;
        int r = idx >> 3, c4 = (idx & 7) * 4;
        *(uint4*)(smraw + QH_OFF + (r * PW + c4) * 4) =
            *(const uint4*)(qph + (size_t)(q0 + r) * 512 + head * 32 + c4);
        *(uint4*)(smraw + QL_OFF + (r * PW + c4) * 4) =
            *(const uint4*)(qpl + (size_t)(q0 + r) * 512 + head * 32 + c4);
    }

    // ---- async K/V chunk load ----
    const int kkey = tid >> 2, kw0 = (tid & 3) * 8;
    auto loadKV = [&](int k0, int bb) {
        uint32_t base = smb + (uint32_t)bb + (kkey * PW + kw0) * 4;
        const uint32_t* ph = kph + (size_t)(k0 + kkey) * 32 + kw0;
        const uint32_t* pl = kpl + (size_t)(k0 + kkey) * 32 + kw0;
        cp16(base,             ph);
        cp16(base + 16,        ph + 4);
        cp16(base + 9216,      pl);
        cp16(base + 9216 + 16, pl + 4);
        const uint32_t* vh = vth + (size_t)kkey * (S_LEN / 2) + (k0 >> 1) + kw0;
        const uint32_t* vl = vtl + (size_t)kkey * (S_LEN / 2) + (k0 >> 1) + kw0;
        cp16(base + 18432,      vh);
        cp16(base + 18432 + 16, vh + 4);
        cp16(base + 27648,      vl);
        cp16(base + 27648 + 16, vl + 4);
        CP_COMMIT();
    };

    loadKV(0, 0);
    __syncthreads();   // Q stores visible

    // ---- Q fragments via ldmatrix ----
    uint32_t Qh[4][4], Ql[4][4];
    {
        uint32_t brow = (uint32_t)(warp * 16 + 8 * (lt & 1) + lr);
        #pragma unroll
        for (int s = 0; s < 4; s++) {
            uint32_t aoff = (brow * PW + 8 * s + 4 * (lt >> 1)) * 4;
            ldsm4(Qh[s][0], Qh[s][1], Qh[s][2], Qh[s][3], smb + QH_OFF + aoff);
            ldsm4(Ql[s][0], Ql[s][1], Ql[s][2], Ql[s][3], smb + QL_OFF + aoff);
        }
    }
    CP_WAIT0();
    __syncthreads();   // buf0 ready; all warps done reading Q region

    float O[8][4];
    #pragma unroll
    for (int j = 0; j < 8; j++)
        #pragma unroll
        for (int e = 0; e < 4; e++) O[j][e] = 0.f;
    float ls0 = 0.f, ls1 = 0.f;

    float Sfc[2][2][4];   // [slot][jj][elem], single accumulation chain

    auto issueS = [&](int bb, int g, int slot) {
        uint32_t kh[2][8], kl[2][8];
        uint32_t krow = (uint32_t)(16 * g + 8 * (lt >> 1) + lr);
        #pragma unroll
        for (int s = 0; s < 4; s++) {
            uint32_t aoff = (krow * PW + 8 * s + 4 * (lt & 1)) * 4;
            ldsm4(kh[0][2*s], kh[0][2*s+1], kh[1][2*s], kh[1][2*s+1],
                  smb + bb + aoff);
            ldsm4(kl[0][2*s], kl[0][2*s+1], kl[1][2*s], kl[1][2*s+1],
                  smb + bb + 9216 + aoff);
        }
        #pragma unroll
        for (int jj = 0; jj < 2; jj++)
            #pragma unroll
            for (int e = 0; e < 4; e++) Sfc[slot][jj][e] = 0.f;
        #pragma unroll
        for (int s = 0; s < 4; s++)
            #pragma unroll
            for (int jj = 0; jj < 2; jj++)
                mma_bf16(Sfc[slot][jj], Qh[s], kh[jj][2 * s], kh[jj][2 * s + 1]);
        #pragma unroll
        for (int s = 0; s < 4; s++)
            #pragma unroll
            for (int jj = 0; jj < 2; jj++)
                mma_bf16(Sfc[slot][jj], Qh[s], kl[jj][2 * s], kl[jj][2 * s + 1]);
        #pragma unroll
        for (int s = 0; s < 4; s++)
            #pragma unroll
            for (int jj = 0; jj < 2; jj++)
                mma_bf16(Sfc[slot][jj], Ql[s], kh[jj][2 * s], kh[jj][2 * s + 1]);
    };

    auto epiPV = [&](int bb, int g, int slot) {
        float ev[2][4];
        #pragma unroll
        for (int jj = 0; jj < 2; jj++)
            #pragma unroll
            for (int e = 0; e < 4; e++)
                ev[jj][e] = __expf(Sfc[slot][jj][e]);
        #pragma unroll
        for (int jj = 0; jj < 2; jj++) {
            ls0 += ev[jj][0] + ev[jj][1];
            ls1 += ev[jj][2] + ev[jj][3];
        }
        uint32_t Ph[4], Pl[4];
        split2(ev[0][0], ev[0][1], Ph[0], Pl[0]);
        split2(ev[0][2], ev[0][3], Ph[1], Pl[1]);
        split2(ev[1][0], ev[1][1], Ph[2], Pl[2]);
        split2(ev[1][2], ev[1][3], Ph[3], Pl[3]);
        uint32_t vh[16], vl[16];
        #pragma unroll
        for (int c = 0; c < 4; c++) {
            uint32_t vrow = (uint32_t)(8 * (2 * c + (lt >> 1)) + lr);
            uint32_t aoff = (vrow * PW + 8 * g + 4 * (lt & 1)) * 4;
            ldsm4(vh[4*c], vh[4*c+1], vh[4*c+2], vh[4*c+3],
                  smb + bb + 18432 + aoff);
            ldsm4(vl[4*c], vl[4*c+1], vl[4*c+2], vl[4*c+3],
                  smb + bb + 27648 + aoff);
        }
        #pragma unroll
        for (int jv = 0; jv < 8; jv++) mma_bf16(O[jv], Ph, vh[2 * jv], vh[2 * jv + 1]);
        #pragma unroll
        for (int jv = 0; jv < 8; jv++) mma_bf16(O[jv], Ph, vl[2 * jv], vl[2 * jv + 1]);
        #pragma unroll
        for (int jv = 0; jv < 8; jv++) mma_bf16(O[jv], Pl, vh[2 * jv], vh[2 * jv + 1]);
    };

    for (int ci = 0; ci < S_LEN / 64; ci++) {
        const int bb = (ci & 1) * BUFB;
        if (ci < S_LEN / 64 - 1) loadKV((ci + 1) * 64, bb ^ BUFB);
        issueS(bb, 0, 0);
        #pragma unroll
        for (int g = 0; g < 4; g++) {
            if (g < 3) issueS(bb, g + 1, (g + 1) & 1);
            epiPV(bb, g, g & 1);
        }
        CP_WAIT0();
        __syncthreads();
    }

    // final row-sum reduction and write
    ls0 += __shfl_xor_sync(FULL, ls0, 1);
    ls0 += __shfl_xor_sync(FULL, ls0, 2);
    ls1 += __shfl_xor_sync(FULL, ls1, 1);
    ls1 += __shfl_xor_sync(FULL, ls1, 2);
    float inv0 = 1.f / ls0, inv1 = 1.f / ls1;
    int row0 = q0 + warp * 16 + gl;
    #pragma unroll
    for (int j = 0; j < 8; j++) {
        int col = head * DKV + j * 8 + 2 * q;
        float2 w0 = { O[j][0] * inv0, O[j][1] * inv0 };
        float2 w1 = { O[j][2] * inv1, O[j][3] * inv1 };
        *(float2*)(out + (size_t)row0 * DMODEL + col) = w0;
        *(float2*)(out + (size_t)(row0 + 8) * DMODEL + col) = w1;
    }
}

// ---------------- launch ----------------------------------------------------
extern "C" void kernel_launch(void* const* d_in, const int* in_sizes, int n_in,
                              void* d_out, int out_size)
{
    const float* q  = (const float*)d_in[0];
    const float* k  = (const float*)d_in[1];
    const float* v  = (const float*)d_in[2];
    const float* Wq = (const float*)d_in[3];
    const float* bq = (const float*)d_in[4];
    const float* Wk = (const float*)d_in[5];
    const float* bk = (const float*)d_in[6];
    const float* Wv = (const float*)d_in[7];
    const float* bv = (const float*)d_in[8];
    const float* Wo = (const float*)d_in[9];
    const float* bo = (const float*)d_in[10];
    float* out = (float*)d_out;

    void* p;
    cudaGetSymbolAddress(&p, g_att);  float* att = (float*)p;
    cudaGetSymbolAddress(&p, g_wqh);  uint32_t* wqh = (uint32_t*)p;
    cudaGetSymbolAddress(&p, g_wql);  uint32_t* wql = (uint32_t*)p;
    cudaGetSymbolAddress(&p, g_wkh);  uint32_t* wkh = (uint32_t*)p;
    cudaGetSymbolAddress(&p, g_wkl);  uint32_t* wkl = (uint32_t*)p;
    cudaGetSymbolAddress(&p, g_wvh);  uint32_t* wvh = (uint32_t*)p;
    cudaGetSymbolAddress(&p, g_wvl);  uint32_t* wvl = (uint32_t*)p;
    cudaGetSymbolAddress(&p, g_woh);  uint32_t* woh = (uint32_t*)p;
    cudaGetSymbolAddress(&p, g_wol);  uint32_t* wol = (uint32_t*)p;
    cudaGetSymbolAddress(&p, g_qph);  uint32_t* qph = (uint32_t*)p;
    cudaGetSymbolAddress(&p, g_qpl);  uint32_t* qpl = (uint32_t*)p;
    cudaGetSymbolAddress(&p, g_kph);  uint32_t* kph = (uint32_t*)p;
    cudaGetSymbolAddress(&p, g_kpl);  uint32_t* kpl = (uint32_t*)p;
    cudaGetSymbolAddress(&p, g_vth);  uint32_t* vth = (uint32_t*)p;
    cudaGetSymbolAddress(&p, g_vtl);  uint32_t* vtl = (uint32_t*)p;

    constexpr int SM_BIG   = (4 * 128 * 20 + 4 * 16 * 136) * 4;  // 75776
    constexpr int SM_SMALL = (4 * 64 * 20 + 4 * 16 * 72) * 4;    // 38912

    cudaFuncSetAttribute((const void*)(bgemm3<128, 128, 32, 2, 4, 1>),
                         cudaFuncAttributeMaxDynamicSharedMemorySize, SM_BIG);
    cudaFuncSetAttribute((const void*)(bgemm3<128, 128, 32, 2, 4, 0>),
                         cudaFuncAttributeMaxDynamicSharedMemorySize, SM_BIG);
    cudaFuncSetAttribute((const void*)(bgemm3<64, 64, 32, 2, 4, 3>),
                         cudaFuncAttributeMaxDynamicSharedMemorySize, SM_SMALL);
    cudaFuncSetAttribute((const void*)mqa_attn_b,
                         cudaFuncAttributeMaxDynamicSharedMemorySize, ATTN_SMEM);

    // weight pre-split (one launch)
    splitAll<<<(2 * 512 * 1024 + 2 * 512 * 64 + 255) / 256, 256>>>(
        Wq, Wo, Wk, Wv, wqh, wql, woh, wol, wkh, wkl, wvh, wvl);

    // Q projection (packed epilogue)
    bgemm3<128, 128, 32, 2, 4, 1>
        <<<dim3(DMODEL / 128, S_LEN / 128), 256, SM_BIG>>>(
            q, wqh, wql, bq, nullptr, qph, qpl,
            nullptr, nullptr, nullptr, nullptr, nullptr, nullptr,
            S_LEN, DMODEL, DMODEL);
    // K + V projections fused (128 CTAs)
    bgemm3<64, 64, 32, 2, 4, 3>
        <<<dim3(2, S_LEN / 64), 256, SM_SMALL>>>(
            k, wkh, wkl, bk, nullptr, kph, kpl,
            v, wvh, wvl, bv, vth, vtl,
            S_LEN, DKV, DMODEL);
    // attention
    mqa_attn_b<<<dim3(S_LEN / 128, HEADS), 256, ATTN_SMEM>>>(qph, qpl, kph, kpl,
                                                             vth, vtl, att);
    // O projection
    bgemm3<128, 128, 32, 2, 4, 0>
        <<<dim3(DMODEL / 128, S_LEN / 128), 256, SM_BIG>>>(
            att, woh, wol, bo, out, nullptr, nullptr,
            nullptr, nullptr, nullptr, nullptr, nullptr, nullptr,
            S_LEN, DMODEL, DMODEL);
}

// round 11
// speedup vs baseline: 1.2072x; 1.1441x over previous
#include <cuda_runtime.h>
#include <cstdint>

#define S_LEN   4096
#define DMODEL  1024
#define HEADS   16
#define DKV     64
#define LOG2E   1.4426950408889634f

// ---------------- scratch ---------------------------------------------------
__device__ float    g_att[S_LEN * DMODEL];       // fp32 [s, h*64+d]
__device__ uint32_t g_wqh[512 * 1024], g_wql[512 * 1024];
__device__ uint32_t g_wkh[512 * 64],   g_wkl[512 * 64];
__device__ uint32_t g_wvh[512 * 64],   g_wvl[512 * 64];
__device__ uint32_t g_woh[512 * 1024], g_wol[512 * 1024];
__device__ uint32_t g_qph[S_LEN * 512], g_qpl[S_LEN * 512];   // fp16 pairs (scaled by log2e)
__device__ uint32_t g_kp[S_LEN * 32];                          // fp16 pairs [key][dk-pair]
__device__ uint32_t g_vth[64 * (S_LEN / 2)], g_vtl[64 * (S_LEN / 2)]; // bf16 [dk][key-pair]

// ---------------- numeric helpers -------------------------------------------
__device__ __forceinline__ void split2(float x, float y, uint32_t& h, uint32_t& l) {
    uint32_t hp;
    asm("cvt.rn.bf16x2.f32 %0,%1,%2;" : "=r"(hp) : "f"(y), "f"(x));
    float hx = __uint_as_float(hp << 16);
    float hy = __uint_as_float(hp & 0xffff0000u);
    asm("cvt.rn.bf16x2.f32 %0,%1,%2;" : "=r"(l) : "f"(y - hy), "f"(x - hx));
    h = hp;
}
__device__ __forceinline__ void splitf16(float x, float y, uint32_t& h, uint32_t& l) {
    uint32_t hp;
    asm("cvt.rn.f16x2.f32 %0,%1,%2;" : "=r"(hp) : "f"(y), "f"(x));
    float hx, hy;
    asm("{.reg .f16 a,b; mov.b32 {a,b},%2; cvt.f32.f16 %0,a; cvt.f32.f16 %1,b;}"
        : "=f"(hx), "=f"(hy) : "r"(hp));
    asm("cvt.rn.f16x2.f32 %0,%1,%2;" : "=r"(l) : "f"(y - hy), "f"(x - hx));
    h = hp;
}
__device__ __forceinline__ uint32_t packf16(float x, float y) {
    uint32_t r;
    asm("cvt.rn.f16x2.f32 %0,%1,%2;" : "=r"(r) : "f"(y), "f"(x));
    return r;
}
__device__ __forceinline__ float ex2f(float x) {
    float r;
    asm("ex2.approx.f32 %0,%1;" : "=f"(r) : "f"(x));
    return r;
}
__device__ __forceinline__ void mma_bf16(float* d, const uint32_t* a,
                                         uint32_t b0, uint32_t b1) {
    asm volatile("mma.sync.aligned.m16n8k16.row.col.f32.bf16.bf16.f32 "
        "{%0,%1,%2,%3},{%4,%5,%6,%7},{%8,%9},{%0,%1,%2,%3};"
        : "+f"(d[0]), "+f"(d[1]), "+f"(d[2]), "+f"(d[3])
        : "r"(a[0]), "r"(a[1]), "r"(a[2]), "r"(a[3]), "r"(b0), "r"(b1));
}
__device__ __forceinline__ void mma_f16(float* d, const uint32_t* a,
                                        uint32_t b0, uint32_t b1) {
    asm volatile("mma.sync.aligned.m16n8k16.row.col.f32.f16.f16.f32 "
        "{%0,%1,%2,%3},{%4,%5,%6,%7},{%8,%9},{%0,%1,%2,%3};"
        : "+f"(d[0]), "+f"(d[1]), "+f"(d[2]), "+f"(d[3])
        : "r"(a[0]), "r"(a[1]), "r"(a[2]), "r"(a[3]), "r"(b0), "r"(b1));
}
__device__ __forceinline__ void ldsm4(uint32_t& r0, uint32_t& r1,
                                      uint32_t& r2, uint32_t& r3, uint32_t addr) {
    asm volatile("ldmatrix.sync.aligned.m8n8.x4.shared.b16 {%0,%1,%2,%3}, [%4];"
                 : "=r"(r0), "=r"(r1), "=r"(r2), "=r"(r3) : "r"(addr));
}
__device__ __forceinline__ uint32_t smem_u32(const void* p) {
    uint32_t a;
    asm("{ .reg .u64 t; cvta.to.shared.u64 t, %1; cvt.u32.u64 %0, t; }"
        : "=r"(a) : "l"(p));
    return a;
}
__device__ __forceinline__ void cp16(uint32_t saddr, const void* g) {
    asm volatile("cp.async.cg.shared.global [%0], [%1], 16;" :: "r"(saddr), "l"(g));
}
#define CP_COMMIT() asm volatile("cp.async.commit_group;" ::: "memory")
#define CP_WAIT0()  asm volatile("cp.async.wait_group 0;"  ::: "memory")

// ---------------- combined weight pre-split (bf16 h/l for GEMM B) -----------
__global__ __launch_bounds__(256)
void splitAll(const float* __restrict__ Wq, const float* __restrict__ Wo,
              const float* __restrict__ Wk, const float* __restrict__ Wv,
              uint32_t* __restrict__ wqh, uint32_t* __restrict__ wql,
              uint32_t* __restrict__ woh, uint32_t* __restrict__ wol,
              uint32_t* __restrict__ wkh, uint32_t* __restrict__ wkl,
              uint32_t* __restrict__ wvh, uint32_t* __restrict__ wvl)
{
    constexpr int BIG = 512 * 1024, SMALL = 512 * 64;
    int idx = blockIdx.x * 256 + threadIdx.x;
    const float* W; uint32_t *Wh, *Wl; int i, N;
    if (idx < BIG)               { W = Wq; Wh = wqh; Wl = wql; i = idx;            N = 1024; }
    else if (idx < 2 * BIG)      { W = Wo; Wh = woh; Wl = wol; i = idx - BIG;      N = 1024; }
    else if (idx < 2 * BIG + SMALL) { W = Wk; Wh = wkh; Wl = wkl; i = idx - 2*BIG; N = 64; }
    else if (idx < 2 * BIG + 2 * SMALL) { W = Wv; Wh = wvh; Wl = wvl; i = idx - 2*BIG - SMALL; N = 64; }
    else return;
    int kp = i / N, n = i - kp * N;
    float a = W[(size_t)(2 * kp) * N + n];
    float b = W[(size_t)(2 * kp + 1) * N + n];
    uint32_t h, l;
    split2(a, b, h, l);
    Wh[i] = h; Wl[i] = l;
}

// ---------------- bf16x3 GEMM, cp.async double-buffered ---------------------
// CMODE 0: C fp32.
// CMODE 3: fused K/V proj — blockIdx.x 0: K-style fp16-pair epilogue (Ch only);
//                           blockIdx.x 1: V-transposed bf16 h/l epilogue.
// CMODE 4: Q-proj epilogue — scale by LOG2E, fp16 hi/lo pairs -> Ch/Cl.
template<int BM, int BN, int BK, int WARPS_M, int WARPS_N, int CMODE>
__global__ __launch_bounds__(WARPS_M * WARPS_N * 32)
void bgemm3(const float* __restrict__ A, const uint32_t* __restrict__ Bh,
            const uint32_t* __restrict__ Bl, const float* __restrict__ bias,
            float* __restrict__ C, uint32_t* __restrict__ Ch,
            uint32_t* __restrict__ Cl,
            const float* __restrict__ A2, const uint32_t* __restrict__ Bh2,
            const uint32_t* __restrict__ Bl2, const float* __restrict__ bias2,
            uint32_t* __restrict__ Ch2, uint32_t* __restrict__ Cl2,
            int M, int N, int K)
{
    constexpr int THREADS = WARPS_M * WARPS_N * 32;
    constexpr int WM = BM / WARPS_M, WN = BN / WARPS_N;
    constexpr int MT = WM / 16, NT = WN / 8;
    constexpr int KW = BK / 2;
    constexpr int AW = KW + 4;
    constexpr int BW = BN + 8;
    constexpr int ASZ = BM * AW;
    constexpr int BSZ = KW * BW;
    constexpr int A_IT = BM * BK / (4 * THREADS);
    constexpr int B_IT = KW * (BN / 4) / THREADS;

    extern __shared__ uint32_t smw[];
    uint32_t* AshB = smw;
    uint32_t* AslB = smw + 2 * ASZ;
    uint32_t* BshB = smw + 4 * ASZ;
    uint32_t* BslB = smw + 4 * ASZ + 2 * BSZ;
    const uint32_t sm_bsh = smem_u32(BshB);
    const uint32_t sm_bsl = smem_u32(BslB);

    bool isV = false;
    if constexpr (CMODE == 3) {
        if (blockIdx.x == 1) {
            isV = true;
            A = A2; Bh = Bh2; Bl = Bl2; bias = bias2; Ch = Ch2; Cl = Cl2;
        }
    }

    const int tid  = threadIdx.x;
    const int warp = tid >> 5, lane = tid & 31;
    const int g = lane >> 2, q = lane & 3;
    const int wm = warp / WARPS_N, wn = warp % WARPS_N;
    const int m0 = blockIdx.y * BM;
    const int n0 = (CMODE == 3) ? 0 : blockIdx.x * BN;

    float acc[MT][NT][4];
    #pragma unroll
    for (int i = 0; i < MT; i++)
        #pragma unroll
        for (int j = 0; j < NT; j++)
            #pragma unroll
            for (int e = 0; e < 4; e++) acc[i][j][e] = 0.f;

    float4 aPF[A_IT];

    auto loadA = [&](int k0) {
        #pragma unroll
        for (int i = 0; i < A_IT; i++) {
            int flat = tid + i * THREADS;
            int r = flat / (BK / 4), c = (flat % (BK / 4)) * 4;
            aPF[i] = *(const float4*)(A + (size_t)(m0 + r) * K + k0 + c);
        }
    };
    auto cpB = [&](int k0, int b) {
        int kp0 = k0 / 2;
        #pragma unroll
        for (int i = 0; i < B_IT; i++) {
            int flat = tid + i * THREADS;
            int kp2 = flat / (BN / 4), c = (flat % (BN / 4)) * 4;
            uint32_t off = (uint32_t)((b * BSZ + kp2 * BW + c) * 4);
            cp16(sm_bsh + off, Bh + (size_t)(kp0 + kp2) * N + n0 + c);
            cp16(sm_bsl + off, Bl + (size_t)(kp0 + kp2) * N + n0 + c);
        }
        CP_COMMIT();
    };
    auto storeA = [&](int b) {
        uint32_t* Ash = AshB + b * ASZ;
        uint32_t* Asl = AslB + b * ASZ;
        #pragma unroll
        for (int i = 0; i < A_IT; i++) {
            int flat = tid + i * THREADS;
            int r = flat / (BK / 4), c = (flat % (BK / 4)) * 4;
            uint32_t h0, l0, h1, l1;
            split2(aPF[i].x, aPF[i].y, h0, l0);
            split2(aPF[i].z, aPF[i].w, h1, l1);
            Ash[r * AW + c / 2] = h0; Ash[r * AW + c / 2 + 1] = h1;
            Asl[r * AW + c / 2] = l0; Asl[r * AW + c / 2 + 1] = l1;
        }
    };

    loadA(0);
    cpB(0, 0);
    storeA(0);
    CP_WAIT0();
    __syncthreads();

    for (int k0 = 0; k0 < K; k0 += BK) {
        const int b = (k0 / BK) & 1;
        const bool more = (k0 + BK < K);
        if (more) { loadA(k0 + BK); cpB(k0 + BK, b ^ 1); }

        const uint32_t* Ash = AshB + b * ASZ;
        const uint32_t* Asl = AslB + b * ASZ;
        const uint32_t* Bsh = BshB + b * BSZ;
        const uint32_t* Bsl = BslB + b * BSZ;

        #pragma unroll
        for (int kk = 0; kk < 2; kk++) {
            const int wof = kk * 8;
            uint32_t Ah[MT][4], Al[MT][4], Bfh[NT][2], Bfl[NT][2];
            #pragma unroll
            for (int i = 0; i < MT; i++) {
                int mr = wm * WM + i * 16;
                Ah[i][0] = Ash[(mr + g) * AW + wof + q];
                Ah[i][1] = Ash[(mr + g + 8) * AW + wof + q];
                Ah[i][2] = Ash[(mr + g) * AW + wof + q + 4];
                Ah[i][3] = Ash[(mr + g + 8) * AW + wof + q + 4];
                Al[i][0] = Asl[(mr + g) * AW + wof + q];
                Al[i][1] = Asl[(mr + g + 8) * AW + wof + q];
                Al[i][2] = Asl[(mr + g) * AW + wof + q + 4];
                Al[i][3] = Asl[(mr + g + 8) * AW + wof + q + 4];
            }
            #pragma unroll
            for (int j = 0; j < NT; j++) {
                int nc = wn * WN + j * 8 + g;
                Bfh[j][0] = Bsh[(wof + q) * BW + nc];
                Bfh[j][1] = Bsh[(wof + q + 4) * BW + nc];
                Bfl[j][0] = Bsl[(wof + q) * BW + nc];
                Bfl[j][1] = Bsl[(wof + q + 4) * BW + nc];
            }
            #pragma unroll
            for (int i = 0; i < MT; i++)
                #pragma unroll
                for (int j = 0; j < NT; j++)
                    mma_bf16(acc[i][j], Ah[i], Bfh[j][0], Bfh[j][1]);
            #pragma unroll
            for (int i = 0; i < MT; i++)
                #pragma unroll
                for (int j = 0; j < NT; j++)
                    mma_bf16(acc[i][j], Ah[i], Bfl[j][0], Bfl[j][1]);
            #pragma unroll
            for (int i = 0; i < MT; i++)
                #pragma unroll
                for (int j = 0; j < NT; j++)
                    mma_bf16(acc[i][j], Al[i], Bfh[j][0], Bfh[j][1]);
        }

        if (more) storeA(b ^ 1);
        CP_WAIT0();
        __syncthreads();
    }

    const unsigned FULL = 0xffffffffu;
    #pragma unroll
    for (int i = 0; i < MT; i++) {
        int row0 = m0 + wm * WM + i * 16 + g;
        #pragma unroll
        for (int j = 0; j < NT; j++) {
            int col = n0 + wn * WN + j * 8 + 2 * q;
            float bx = bias[col], by = bias[col + 1];
            float v0 = acc[i][j][0] + bx, v1 = acc[i][j][1] + by;
            float v2 = acc[i][j][2] + bx, v3 = acc[i][j][3] + by;
            if constexpr (CMODE == 0) {
                float2 w0 = { v0, v1 }, w1 = { v2, v3 };
                *(float2*)(C + (size_t)row0 * N + col) = w0;
                *(float2*)(C + (size_t)(row0 + 8) * N + col) = w1;
            } else if constexpr (CMODE == 4) {
                // Q-proj: scale by log2e, fp16 hi/lo pairs
                v0 *= LOG2E; v1 *= LOG2E; v2 *= LOG2E; v3 *= LOG2E;
                uint32_t h, l;
                splitf16(v0, v1, h, l);
                Ch[(size_t)row0 * (N / 2) + col / 2] = h;
                Cl[(size_t)row0 * (N / 2) + col / 2] = l;
                splitf16(v2, v3, h, l);
                Ch[(size_t)(row0 + 8) * (N / 2) + col / 2] = h;
                Cl[(size_t)(row0 + 8) * (N / 2) + col / 2] = l;
            } else {
                if (!isV) {
                    // K-proj: single fp16 pairs
                    Ch[(size_t)row0 * (N / 2) + col / 2] = packf16(v0, v1);
                    Ch[(size_t)(row0 + 8) * (N / 2) + col / 2] = packf16(v2, v3);
                } else {
                    // V-proj: transposed bf16 hi/lo key-pairs
                    float p0 = __shfl_xor_sync(FULL, v0, 4);
                    float p1 = __shfl_xor_sync(FULL, v1, 4);
                    float p2 = __shfl_xor_sync(FULL, v2, 4);
                    float p3 = __shfl_xor_sync(FULL, v3, 4);
                    uint32_t h, l;
                    if ((g & 1) == 0) {
                        split2(v0, p0, h, l);
                        Ch[(size_t)col * (S_LEN / 2) + row0 / 2] = h;
                        Cl[(size_t)col * (S_LEN / 2) + row0 / 2] = l;
                        split2(v2, p2, h, l);
                        Ch[(size_t)col * (S_LEN / 2) + (row0 + 8) / 2] = h;
                        Cl[(size_t)col * (S_LEN / 2) + (row0 + 8) / 2] = l;
                    } else {
                        split2(p1, v1, h, l);
                        Ch[(size_t)(col + 1) * (S_LEN / 2) + (row0 - 1) / 2] = h;
                        Cl[(size_t)(col + 1) * (S_LEN / 2) + (row0 - 1) / 2] = l;
                        split2(p3, v3, h, l);
                        Ch[(size_t)(col + 1) * (S_LEN / 2) + (row0 + 7) / 2] = h;
                        Cl[(size_t)(col + 1) * (S_LEN / 2) + (row0 + 7) / 2] = l;
                    }
                }
            }
        }
    }
}

// ---------------- flash MQA attention (fp16 2-pass S, bf16x3 PV) ------------
// smem: 2 buffers x [K 9216 | VH 9216 | VL 9216]; Q (fp16 h/l) above.
#define PW   36
#define BUFB 27648
#define QH_OFF 55296
#define QL_OFF 73728
#define ATTN_SMEM 92160

__global__ __launch_bounds__(256, 2)
void mqa_attn_c(const uint32_t* __restrict__ qph, const uint32_t* __restrict__ qpl,
                const uint32_t* __restrict__ kp,
                const uint32_t* __restrict__ vth, const uint32_t* __restrict__ vtl,
                float* __restrict__ out)
{
    extern __shared__ char smraw[];
    const uint32_t smb = smem_u32(smraw);
    const int tid  = threadIdx.x;
    const int warp = tid >> 5, lane = tid & 31;
    const int gl = lane >> 2, q = lane & 3;
    const int lt = lane >> 3, lr = lane & 7;
    const int head = blockIdx.y;
    const int q0 = blockIdx.x * 128;
    const unsigned FULL = 0xffffffffu;

    // ---- stage packed Q (fp16, pre-scaled by log2e) ----
    #pragma unroll
    for (int i = 0; i < 4; i++) {
        int idx = tid + i * 256;
        int r = idx >> 3, c4 = (idx & 7) * 4;
        *(uint4*)(smraw + QH_OFF + (r * PW + c4) * 4) =
            *(const uint4*)(qph + (size_t)(q0 + r) * 512 + head * 32 + c4);
        *(uint4*)(smraw + QL_OFF + (r * PW + c4) * 4) =
            *(const uint4*)(qpl + (size_t)(q0 + r) * 512 + head * 32 + c4);
    }

    // ---- async K/V chunk load ----
    const int kkey = tid >> 2, kw0 = (tid & 3) * 8;
    auto loadKV = [&](int k0, int bb) {
        uint32_t base = smb + (uint32_t)bb + (kkey * PW + kw0) * 4;
        const uint32_t* ph = kp + (size_t)(k0 + kkey) * 32 + kw0;
        cp16(base,      ph);
        cp16(base + 16, ph + 4);
        const uint32_t* vh = vth + (size_t)kkey * (S_LEN / 2) + (k0 >> 1) + kw0;
        const uint32_t* vl = vtl + (size_t)kkey * (S_LEN / 2) + (k0 >> 1) + kw0;
        cp16(base + 9216,       vh);
        cp16(base + 9216 + 16,  vh + 4);
        cp16(base + 18432,      vl);
        cp16(base + 18432 + 16, vl + 4);
        CP_COMMIT();
    };

    loadKV(0, 0);
    __syncthreads();   // Q stores visible

    // ---- Q fragments via ldmatrix ----
    uint32_t Qh[4][4], Ql[4][4];
    {
        uint32_t brow = (uint32_t)(warp * 16 + 8 * (lt & 1) + lr);
        #pragma unroll
        for (int s = 0; s < 4; s++) {
            uint32_t aoff = (brow * PW + 8 * s + 4 * (lt >> 1)) * 4;
            ldsm4(Qh[s][0], Qh[s][1], Qh[s][2], Qh[s][3], smb + QH_OFF + aoff);
            ldsm4(Ql[s][0], Ql[s][1], Ql[s][2], Ql[s][3], smb + QL_OFF + aoff);
        }
    }
    CP_WAIT0();
    __syncthreads();

    float O[8][4];
    #pragma unroll
    for (int j = 0; j < 8; j++)
        #pragma unroll
        for (int e = 0; e < 4; e++) O[j][e] = 0.f;
    float ls0 = 0.f, ls1 = 0.f;

    float Sfc[2][2][4];

    auto issueS = [&](int bb, int g, int slot) {
        uint32_t kf[2][8];
        uint32_t krow = (uint32_t)(16 * g + 8 * (lt >> 1) + lr);
        #pragma unroll
        for (int s = 0; s < 4; s++) {
            uint32_t aoff = (krow * PW + 8 * s + 4 * (lt & 1)) * 4;
            ldsm4(kf[0][2*s], kf[0][2*s+1], kf[1][2*s], kf[1][2*s+1],
                  smb + bb + aoff);
        }
        #pragma unroll
        for (int jj = 0; jj < 2; jj++)
            #pragma unroll
            for (int e = 0; e < 4; e++) Sfc[slot][jj][e] = 0.f;
        #pragma unroll
        for (int s = 0; s < 4; s++)
            #pragma unroll
            for (int jj = 0; jj < 2; jj++)
                mma_f16(Sfc[slot][jj], Qh[s], kf[jj][2 * s], kf[jj][2 * s + 1]);
        #pragma unroll
        for (int s = 0; s < 4; s++)
            #pragma unroll
            for (int jj = 0; jj < 2; jj++)
                mma_f16(Sfc[slot][jj], Ql[s], kf[jj][2 * s], kf[jj][2 * s + 1]);
    };

    auto epiPV = [&](int bb, int g, int slot) {
        float ev[2][4];
        #pragma unroll
        for (int jj = 0; jj < 2; jj++)
            #pragma unroll
            for (int e = 0; e < 4; e++)
                ev[jj][e] = ex2f(Sfc[slot][jj][e]);
        #pragma unroll
        for (int jj = 0; jj < 2; jj++) {
            ls0 += ev[jj][0] + ev[jj][1];
            ls1 += ev[jj][2] + ev[jj][3];
        }
        uint32_t Ph[4], Pl[4];
        split2(ev[0][0], ev[0][1], Ph[0], Pl[0]);
        split2(ev[0][2], ev[0][3], Ph[1], Pl[1]);
        split2(ev[1][0], ev[1][1], Ph[2], Pl[2]);
        split2(ev[1][2], ev[1][3], Ph[3], Pl[3]);
        uint32_t vh[16], vl[16];
        #pragma unroll
        for (int c = 0; c < 4; c++) {
            uint32_t vrow = (uint32_t)(8 * (2 * c + (lt >> 1)) + lr);
            uint32_t aoff = (vrow * PW + 8 * g + 4 * (lt & 1)) * 4;
            ldsm4(vh[4*c], vh[4*c+1], vh[4*c+2], vh[4*c+3],
                  smb + bb + 9216 + aoff);
            ldsm4(vl[4*c], vl[4*c+1], vl[4*c+2], vl[4*c+3],
                  smb + bb + 18432 + aoff);
        }
        #pragma unroll
        for (int jv = 0; jv < 8; jv++) mma_bf16(O[jv], Ph, vh[2 * jv], vh[2 * jv + 1]);
        #pragma unroll
        for (int jv = 0; jv < 8; jv++) mma_bf16(O[jv], Ph, vl[2 * jv], vl[2 * jv + 1]);
        #pragma unroll
        for (int jv = 0; jv < 8; jv++) mma_bf16(O[jv], Pl, vh[2 * jv], vh[2 * jv + 1]);
    };

    for (int ci = 0; ci < S_LEN / 64; ci++) {
        const int bb = (ci & 1) * BUFB;
        if (ci < S_LEN / 64 - 1) loadKV((ci + 1) * 64, bb ^ BUFB);
        issueS(bb, 0, 0);
        #pragma unroll
        for (int g = 0; g < 4; g++) {
            if (g < 3) issueS(bb, g + 1, (g + 1) & 1);
            epiPV(bb, g, g & 1);
        }
        CP_WAIT0();
        __syncthreads();
    }

    // final row-sum reduction and write
    ls0 += __shfl_xor_sync(FULL, ls0, 1);
    ls0 += __shfl_xor_sync(FULL, ls0, 2);
    ls1 += __shfl_xor_sync(FULL, ls1, 1);
    ls1 += __shfl_xor_sync(FULL, ls1, 2);
    float inv0 = 1.f / ls0, inv1 = 1.f / ls1;
    int row0 = q0 + warp * 16 + gl;
    #pragma unroll
    for (int j = 0; j < 8; j++) {
        int col = head * DKV + j * 8 + 2 * q;
        float2 w0 = { O[j][0] * inv0, O[j][1] * inv0 };
        float2 w1 = { O[j][2] * inv1, O[j][3] * inv1 };
        *(float2*)(out + (size_t)row0 * DMODEL + col) = w0;
        *(float2*)(out + (size_t)(row0 + 8) * DMODEL + col) = w1;
    }
}

// ---------------- launch ----------------------------------------------------
extern "C" void kernel_launch(void* const* d_in, const int* in_sizes, int n_in,
                              void* d_out, int out_size)
{
    const float* q  = (const float*)d_in[0];
    const float* k  = (const float*)d_in[1];
    const float* v  = (const float*)d_in[2];
    const float* Wq = (const float*)d_in[3];
    const float* bq = (const float*)d_in[4];
    const float* Wk = (const float*)d_in[5];
    const float* bk = (const float*)d_in[6];
    const float* Wv = (const float*)d_in[7];
    const float* bv = (const float*)d_in[8];
    const float* Wo = (const float*)d_in[9];
    const float* bo = (const float*)d_in[10];
    float* out = (float*)d_out;

    void* p;
    cudaGetSymbolAddress(&p, g_att);  float* att = (float*)p;
    cudaGetSymbolAddress(&p, g_wqh);  uint32_t* wqh = (uint32_t*)p;
    cudaGetSymbolAddress(&p, g_wql);  uint32_t* wql = (uint32_t*)p;
    cudaGetSymbolAddress(&p, g_wkh);  uint32_t* wkh = (uint32_t*)p;
    cudaGetSymbolAddress(&p, g_wkl);  uint32_t* wkl = (uint32_t*)p;
    cudaGetSymbolAddress(&p, g_wvh);  uint32_t* wvh = (uint32_t*)p;
    cudaGetSymbolAddress(&p, g_wvl);  uint32_t* wvl = (uint32_t*)p;
    cudaGetSymbolAddress(&p, g_woh);  uint32_t* woh = (uint32_t*)p;
    cudaGetSymbolAddress(&p, g_wol);  uint32_t* wol = (uint32_t*)p;
    cudaGetSymbolAddress(&p, g_qph);  uint32_t* qph = (uint32_t*)p;
    cudaGetSymbolAddress(&p, g_qpl);  uint32_t* qpl = (uint32_t*)p;
    cudaGetSymbolAddress(&p, g_kp);   uint32_t* kpp = (uint32_t*)p;
    cudaGetSymbolAddress(&p, g_vth);  uint32_t* vth = (uint32_t*)p;
    cudaGetSymbolAddress(&p, g_vtl);  uint32_t* vtl = (uint32_t*)p;

    constexpr int SM_BIG   = (4 * 128 * 20 + 4 * 16 * 136) * 4;  // 75776
    constexpr int SM_SMALL = (4 * 64 * 20 + 4 * 16 * 72) * 4;    // 38912

    cudaFuncSetAttribute((const void*)(bgemm3<128, 128, 32, 2, 4, 4>),
                         cudaFuncAttributeMaxDynamicSharedMemorySize, SM_BIG);
    cudaFuncSetAttribute((const void*)(bgemm3<128, 128, 32, 2, 4, 0>),
                         cudaFuncAttributeMaxDynamicSharedMemorySize, SM_BIG);
    cudaFuncSetAttribute((const void*)(bgemm3<64, 64, 32, 2, 4, 3>),
                         cudaFuncAttributeMaxDynamicSharedMemorySize, SM_SMALL);
    cudaFuncSetAttribute((const void*)mqa_attn_c,
                         cudaFuncAttributeMaxDynamicSharedMemorySize, ATTN_SMEM);

    // weight pre-split
    splitAll<<<(2 * 512 * 1024 + 2 * 512 * 64 + 255) / 256, 256>>>(
        Wq, Wo, Wk, Wv, wqh, wql, woh, wol, wkh, wkl, wvh, wvl);

    // Q projection (fp16 h/l, log2e-scaled epilogue)
    bgemm3<128, 128, 32, 2, 4, 4>
        <<<dim3(DMODEL / 128, S_LEN / 128), 256, SM_BIG>>>(
            q, wqh, wql, bq, nullptr, qph, qpl,
            nullptr, nullptr, nullptr, nullptr, nullptr, nullptr,
            S_LEN, DMODEL, DMODEL);
    // K + V projections fused (K: fp16 pairs; V: transposed bf16 h/l)
    bgemm3<64, 64, 32, 2, 4, 3>
        <<<dim3(2, S_LEN / 64), 256, SM_SMALL>>>(
            k, wkh, wkl, bk, nullptr, kpp, nullptr,
            v, wvh, wvl, bv, vth, vtl,
            S_LEN, DKV, DMODEL);
    // attention
    mqa_attn_c<<<dim3(S_LEN / 128, HEADS), 256, ATTN_SMEM>>>(qph, qpl, kpp,
                                                             vth, vtl, att);
    // O projection
    bgemm3<128, 128, 32, 2, 4, 0>
        <<<dim3(DMODEL / 128, S_LEN / 128), 256, SM_BIG>>>(
            att, woh, wol, bo, out, nullptr, nullptr,
            nullptr, nullptr, nullptr, nullptr, nullptr, nullptr,
            S_LEN, DMODEL, DMODEL);
}